// round 7
// baseline (speedup 1.0000x reference)
#include <cuda_runtime.h>
#include <math.h>

#define GDIM 4
#define SDIM 2048
#define TTOT 8192
#define MDIM 1024
#define EDIM 64
#define GEMM_BLOCKS 128      // 64 tokens each
#define FILL_BLOCKS 168
#define GRID_TOTAL  (GEMM_BLOCKS + FILL_BLOCKS)   // 296 = 2 per SM

typedef unsigned long long ull;

__device__ int      g_idx[TTOT];
__device__ float    g_gate[TTOT];
__device__ int      g_pos[TTOT];
__device__ int      g_counts[GDIM * EDIM];
__device__ float    g_proxy[GEMM_BLOCKS * EDIM];
__device__ unsigned g_route_done, g_pos_done, g_fill_done;

__global__ void k_reset() {
    g_route_done = 0; g_pos_done = 0; g_fill_done = 0;
}

// block-wide spin on a global counter (thread 0 polls, then block syncs)
__device__ __forceinline__ void spin_until(unsigned* ctr, unsigned tgt) {
    if (threadIdx.x == 0) {
        while (atomicAdd(ctr, 0u) < tgt) __nanosleep(256);
    }
    __syncthreads();
    __threadfence();
}

// ---------------------------------------------------------------------------
// One persistent kernel, two roles:
//  blocks [0,128):  gemm -> (blocks 0-3: pos scan) -> (block 0: aux) -> patch
//  blocks [128,296): stream-store zeros over a static contiguous slice
// ---------------------------------------------------------------------------
__global__ __launch_bounds__(256, 2)
void k_fused(const float* __restrict__ x, const float* __restrict__ Wt,
             float* __restrict__ out, int C, size_t N) {
    __shared__ char sm_raw[33664];      // union: gemm tiles / pos arrays / aux red
    const int tid = threadIdx.x;
    const int b = blockIdx.x;

    // ===================== FILL ROLE =====================
    if (b >= GEMM_BLOCKS) {
        const int fb = b - GEMM_BLOCKS;
        const size_t n4 = (2 * N) >> 2;
        const size_t lo = n4 * (size_t)fb / FILL_BLOCKS;
        const size_t hi = n4 * (size_t)(fb + 1) / FILL_BLOCKS;
        float4* o4 = (float4*)out;
        const float4 z = make_float4(0.f, 0.f, 0.f, 0.f);
        for (size_t i = lo + tid; i < hi; i += 256) __stcs(o4 + i, z);
        __threadfence();
        __syncthreads();
        if (tid == 0) atomicAdd(&g_fill_done, 1u);
        return;
    }

    // ===================== GEMM ROLE =====================
    {
        float* xls  = (float*)sm_raw;        // 64*65 floats
        float* ws   = xls + 64 * 65;         // 64*64 floats
        float* isum = ws + 64 * 64;          // 64 floats

        const int w = tid >> 5;
        const int l = tid & 31;
        const int tb = b * 64;

        ull acc[2][4] = {};

        for (int ch = 0; ch < 16; ++ch) {
            {
                int t = tid >> 2, q = tid & 3;
                const float4* src = (const float4*)(x + (size_t)(tb + t) * MDIM + ch * 64 + q * 16);
                float4 v0 = src[0], v1 = src[1], v2 = src[2], v3 = src[3];
                float* d = &xls[t * 65 + q * 16];
                d[0]=v0.x; d[1]=v0.y; d[2]=v0.z; d[3]=v0.w;
                d[4]=v1.x; d[5]=v1.y; d[6]=v1.z; d[7]=v1.w;
                d[8]=v2.x; d[9]=v2.y; d[10]=v2.z; d[11]=v2.w;
                d[12]=v3.x; d[13]=v3.y; d[14]=v3.z; d[15]=v3.w;
            }
            {
                const float4* src = (const float4*)(Wt + (size_t)(ch * 64) * EDIM);
                float4* dst = (float4*)ws;
#pragma unroll
                for (int j = 0; j < 4; ++j) dst[tid + j * 256] = src[tid + j * 256];
            }
            __syncthreads();

#pragma unroll 8
            for (int mm = 0; mm < 64; ++mm) {
                float xa = xls[l * 65 + mm];
                float xb = xls[(l + 32) * 65 + mm];
                ull xa2, xb2;
                asm("mov.b64 %0, {%1, %1};" : "=l"(xa2) : "f"(xa));
                asm("mov.b64 %0, {%1, %1};" : "=l"(xb2) : "f"(xb));
                const ull* wp = (const ull*)&ws[mm * 64 + w * 8];
#pragma unroll
                for (int p = 0; p < 4; ++p) {
                    ull w2 = wp[p];
                    asm("fma.rn.f32x2 %0, %1, %2, %0;" : "+l"(acc[0][p]) : "l"(w2), "l"(xa2));
                    asm("fma.rn.f32x2 %0, %1, %2, %0;" : "+l"(acc[1][p]) : "l"(w2), "l"(xb2));
                }
            }
            __syncthreads();
        }

#pragma unroll
        for (int tt = 0; tt < 2; ++tt) {
            int t = l + 32 * tt;
#pragma unroll
            for (int p = 0; p < 4; ++p) {
                float lo, hi;
                asm("mov.b64 {%0, %1}, %2;" : "=f"(lo), "=f"(hi) : "l"(acc[tt][p]));
                xls[t * 65 + w * 8 + 2 * p]     = lo;
                xls[t * 65 + w * 8 + 2 * p + 1] = hi;
            }
        }
        __syncthreads();

        if (tid < 64) {
            const int t = tid;
            float mx = -1e30f; int am = 0;
            for (int e = 0; e < EDIM; ++e) {
                float v = xls[t * 65 + e];
                if (v > mx) { mx = v; am = e; }
            }
            float sm = 0.0f;
            for (int e = 0; e < EDIM; ++e) {
                float p = expf(xls[t * 65 + e] - mx);
                xls[t * 65 + e] = p;
                sm += p;
            }
            float inv = 1.0f / sm;
            isum[t] = inv;
            g_idx[tb + t]  = am;
            g_gate[tb + t] = inv;
        }
        __syncthreads();

        if (tid < 64) {
            const int e = tid;
            float s = 0.0f;
            for (int t = 0; t < 64; ++t) s += xls[t * 65 + e] * isum[t];
            g_proxy[b * 64 + e] = s;
        }
        __threadfence();
        __syncthreads();
        if (tid == 0) atomicAdd(&g_route_done, 1u);
    }

    // ============ POS SCAN (blocks 0..3, one group each) ============
    if (b < GDIM) {
        spin_until(&g_route_done, GEMM_BLOCKS);
        int* idx_s = (int*)sm_raw;          // 2048
        int* cnt_s = idx_s + 2048;          // 1024
        int* pos_s = cnt_s + 1024;          // 2048   (20KB total)
        const int g = b;

        for (int i = tid; i < 2048; i += 256) idx_s[i] = __ldcg(&g_idx[g * 2048 + i]);
        __syncthreads();

#pragma unroll
        for (int k = 0; k < 4; ++k) {
            int wi = tid + 256 * k;         // (chunk, expert) worker
            int c = wi >> 6, e = wi & 63;
            int cnt = 0;
#pragma unroll 8
            for (int i = 0; i < 128; ++i) cnt += (idx_s[c * 128 + i] == e);
            cnt_s[c * 64 + e] = cnt;
        }
        __syncthreads();

#pragma unroll
        for (int k = 0; k < 4; ++k) {
            int wi = tid + 256 * k;
            int c = wi >> 6, e = wi & 63;
            int pre = 0;
            for (int cc = 0; cc < c; ++cc) pre += cnt_s[cc * 64 + e];
            if (c == 15) g_counts[g * 64 + e] = pre + cnt_s[c * 64 + e];
            int run = pre;
            for (int i = 0; i < 128; ++i) {
                int s = c * 128 + i;
                if (idx_s[s] == e) pos_s[s] = run++;
            }
        }
        __syncthreads();

        for (int i = tid; i < 2048; i += 256) g_pos[g * 2048 + i] = pos_s[i];
        __threadfence();
        __syncthreads();
        if (tid == 0) atomicAdd(&g_pos_done, 1u);
    }

    // ============ AUX LOSS (block 0) ============
    if (b == 0) {
        spin_until(&g_pos_done, GDIM);
        float* red = (float*)sm_raw;
        const int g = tid >> 6;
        const int e = tid & 63;
        float px = 0.0f;
        for (int bb = 0; bb < 32; ++bb) px += __ldcg(&g_proxy[(g * 32 + bb) * 64 + e]);
        const float denom = 1.0f + 1e-6f;
        float d1 = ((float)__ldcg(&g_counts[g * 64 + e]) / (float)SDIM) / denom;
        float dp = (px / (float)SDIM) / denom;
        red[tid] = d1 * dp;
        __syncthreads();
        for (int s = 128; s > 0; s >>= 1) {
            if (tid < s) red[tid] += red[tid + s];
            __syncthreads();
        }
        if (tid == 0)
            out[2 * N] = (red[0] / 256.0f) * ((float)EDIM * (float)EDIM * 0.01f);
    }

    // ============ PATCH (all gemm blocks, own 64 tokens) ============
    spin_until(&g_pos_done, GDIM);
    spin_until(&g_fill_done, FILL_BLOCKS);
    if (tid < 64) {
        int t = b * 64 + tid;
        int p = __ldcg(&g_pos[t]);
        if (p < C) {
            int e = __ldcg(&g_idx[t]);
            float gv = __ldcg(&g_gate[t]);
            size_t base = ((size_t)t * EDIM + e) * (size_t)C + p;
            out[base]     = gv;
            out[N + base] = 1.0f;
        }
    }
}

// ---------------------------------------------------------------------------
extern "C" void kernel_launch(void* const* d_in, const int* in_sizes, int n_in,
                              void* d_out, int out_size) {
    const float* x  = (const float*)d_in[0];
    const float* Wt = (const float*)d_in[1];
    float* out = (float*)d_out;

    size_t N = ((size_t)out_size - 1) / 2;
    int C = (int)(N / ((size_t)TTOT * EDIM));   // 160

    k_reset<<<1, 1>>>();
    k_fused<<<GRID_TOTAL, 256>>>(x, Wt, out, C, N);
}

// round 9
// speedup vs baseline: 1.1310x; 1.1310x over previous
#include <cuda_runtime.h>
#include <math.h>

#define GDIM 4
#define SDIM 2048
#define TTOT 8192
#define MDIM 1024
#define EDIM 64
#define GEMM_BLOCKS 128        // 64 tokens each
#define FILL_BLOCKS 464
#define GRID_TOTAL  (GEMM_BLOCKS + FILL_BLOCKS)   // 592 = 4 per SM, one wave

typedef unsigned long long ull;

__device__ int      g_idx[TTOT];
__device__ float    g_gate[TTOT];
__device__ int      g_pos[TTOT];
__device__ int      g_counts[GDIM * EDIM];
__device__ float    g_proxy[GEMM_BLOCKS * EDIM];
__device__ unsigned g_route_done, g_pos_done, g_fill_done;

__global__ void k_reset() {
    g_route_done = 0; g_pos_done = 0; g_fill_done = 0;
}

__device__ __forceinline__ void spin_until(unsigned* ctr, unsigned tgt) {
    if (threadIdx.x == 0) {
        while (atomicAdd(ctr, 0u) < tgt) __nanosleep(256);
    }
    __syncthreads();
    __threadfence();
}

// ---------------------------------------------------------------------------
// One persistent kernel, one wave (592 blocks = 4/SM), two roles:
//  blocks [0,128):   gemm -> (blocks 0-3: pos scan) -> (block 0: aux) -> patch
//  blocks [128,592): stream-store zeros over a static contiguous slice
// __launch_bounds__(256,4) caps regs at 64 so all 4 blocks/SM are co-resident;
// ~28 storing warps/SM saturates STG.128 issue (12cyc/warp) -> DRAM-bound fill.
// ---------------------------------------------------------------------------
__global__ __launch_bounds__(256, 4)
void k_fused(const float* __restrict__ x, const float* __restrict__ Wt,
             float* __restrict__ out, int C, size_t N) {
    __shared__ char sm_raw[33664];
    const int tid = threadIdx.x;
    const int b = blockIdx.x;

    // ===================== FILL ROLE =====================
    if (b >= GEMM_BLOCKS) {
        const int fb = b - GEMM_BLOCKS;
        const size_t n4 = (2 * N) >> 2;
        const size_t lo = n4 * (size_t)fb / FILL_BLOCKS;
        const size_t hi = n4 * (size_t)(fb + 1) / FILL_BLOCKS;
        float4* o4 = (float4*)out;
        const float4 z = make_float4(0.f, 0.f, 0.f, 0.f);
        size_t i = lo + tid;
        for (; i + 768 < hi; i += 1024) {
            __stcs(o4 + i, z);
            __stcs(o4 + i + 256, z);
            __stcs(o4 + i + 512, z);
            __stcs(o4 + i + 768, z);
        }
        for (; i < hi; i += 256) __stcs(o4 + i, z);
        __threadfence();
        __syncthreads();
        if (tid == 0) atomicAdd(&g_fill_done, 1u);
        return;
    }

    // ===================== GEMM ROLE =====================
    {
        float* xls  = (float*)sm_raw;        // 64*65 floats
        float* ws   = xls + 64 * 65;         // 64*64 floats
        float* isum = ws + 64 * 64;          // 64 floats

        const int w = tid >> 5;
        const int l = tid & 31;
        const int tb = b * 64;

        ull acc[2][4] = {};

        for (int ch = 0; ch < 16; ++ch) {
            {
                int t = tid >> 2, q = tid & 3;
                const float4* src = (const float4*)(x + (size_t)(tb + t) * MDIM + ch * 64 + q * 16);
                float4 v0 = src[0], v1 = src[1], v2 = src[2], v3 = src[3];
                float* d = &xls[t * 65 + q * 16];
                d[0]=v0.x; d[1]=v0.y; d[2]=v0.z; d[3]=v0.w;
                d[4]=v1.x; d[5]=v1.y; d[6]=v1.z; d[7]=v1.w;
                d[8]=v2.x; d[9]=v2.y; d[10]=v2.z; d[11]=v2.w;
                d[12]=v3.x; d[13]=v3.y; d[14]=v3.z; d[15]=v3.w;
            }
            {
                const float4* src = (const float4*)(Wt + (size_t)(ch * 64) * EDIM);
                float4* dst = (float4*)ws;
#pragma unroll
                for (int j = 0; j < 4; ++j) dst[tid + j * 256] = src[tid + j * 256];
            }
            __syncthreads();

#pragma unroll 8
            for (int mm = 0; mm < 64; ++mm) {
                float xa = xls[l * 65 + mm];
                float xb = xls[(l + 32) * 65 + mm];
                ull xa2, xb2;
                asm("mov.b64 %0, {%1, %1};" : "=l"(xa2) : "f"(xa));
                asm("mov.b64 %0, {%1, %1};" : "=l"(xb2) : "f"(xb));
                const ull* wp = (const ull*)&ws[mm * 64 + w * 8];
#pragma unroll
                for (int p = 0; p < 4; ++p) {
                    ull w2 = wp[p];
                    asm("fma.rn.f32x2 %0, %1, %2, %0;" : "+l"(acc[0][p]) : "l"(w2), "l"(xa2));
                    asm("fma.rn.f32x2 %0, %1, %2, %0;" : "+l"(acc[1][p]) : "l"(w2), "l"(xb2));
                }
            }
            __syncthreads();
        }

#pragma unroll
        for (int tt = 0; tt < 2; ++tt) {
            int t = l + 32 * tt;
#pragma unroll
            for (int p = 0; p < 4; ++p) {
                float lo, hi;
                asm("mov.b64 {%0, %1}, %2;" : "=f"(lo), "=f"(hi) : "l"(acc[tt][p]));
                xls[t * 65 + w * 8 + 2 * p]     = lo;
                xls[t * 65 + w * 8 + 2 * p + 1] = hi;
            }
        }
        __syncthreads();

        if (tid < 64) {
            const int t = tid;
            float mx = -1e30f; int am = 0;
            for (int e = 0; e < EDIM; ++e) {
                float v = xls[t * 65 + e];
                if (v > mx) { mx = v; am = e; }
            }
            float sm = 0.0f;
            for (int e = 0; e < EDIM; ++e) {
                float p = expf(xls[t * 65 + e] - mx);
                xls[t * 65 + e] = p;
                sm += p;
            }
            float inv = 1.0f / sm;
            isum[t] = inv;
            g_idx[tb + t]  = am;
            g_gate[tb + t] = inv;
        }
        __syncthreads();

        if (tid < 64) {
            const int e = tid;
            float s = 0.0f;
            for (int t = 0; t < 64; ++t) s += xls[t * 65 + e] * isum[t];
            g_proxy[b * 64 + e] = s;
        }
        __threadfence();
        __syncthreads();
        if (tid == 0) atomicAdd(&g_route_done, 1u);
    }

    // ============ POS SCAN (blocks 0..3, one group each) ============
    if (b < GDIM) {
        spin_until(&g_route_done, GEMM_BLOCKS);
        int* idx_s = (int*)sm_raw;          // 2048
        int* cnt_s = idx_s + 2048;          // 1024
        int* pos_s = cnt_s + 1024;          // 2048
        const int g = b;

        for (int i = tid; i < 2048; i += 256) idx_s[i] = __ldcg(&g_idx[g * 2048 + i]);
        __syncthreads();

#pragma unroll
        for (int k = 0; k < 4; ++k) {
            int wi = tid + 256 * k;         // (chunk, expert)
            int c = wi >> 6, e = wi & 63;
            int cnt = 0;
#pragma unroll 8
            for (int i = 0; i < 128; ++i) cnt += (idx_s[c * 128 + i] == e);
            cnt_s[c * 64 + e] = cnt;
        }
        __syncthreads();

#pragma unroll
        for (int k = 0; k < 4; ++k) {
            int wi = tid + 256 * k;
            int c = wi >> 6, e = wi & 63;
            int pre = 0;
            for (int cc = 0; cc < c; ++cc) pre += cnt_s[cc * 64 + e];
            if (c == 15) g_counts[g * 64 + e] = pre + cnt_s[c * 64 + e];
            int run = pre;
            for (int i = 0; i < 128; ++i) {
                int s = c * 128 + i;
                if (idx_s[s] == e) pos_s[s] = run++;
            }
        }
        __syncthreads();

        for (int i = tid; i < 2048; i += 256) g_pos[g * 2048 + i] = pos_s[i];
        __threadfence();
        __syncthreads();
        if (tid == 0) atomicAdd(&g_pos_done, 1u);
    }

    // ============ AUX LOSS (block 0) ============
    if (b == 0) {
        spin_until(&g_pos_done, GDIM);
        float* red = (float*)sm_raw;
        const int g = tid >> 6;
        const int e = tid & 63;
        float px = 0.0f;
        for (int bb = 0; bb < 32; ++bb) px += __ldcg(&g_proxy[(g * 32 + bb) * 64 + e]);
        const float denom = 1.0f + 1e-6f;
        float d1 = ((float)__ldcg(&g_counts[g * 64 + e]) / (float)SDIM) / denom;
        float dp = (px / (float)SDIM) / denom;
        red[tid] = d1 * dp;
        __syncthreads();
        for (int s = 128; s > 0; s >>= 1) {
            if (tid < s) red[tid] += red[tid + s];
            __syncthreads();
        }
        if (tid == 0)
            out[2 * N] = (red[0] / 256.0f) * ((float)EDIM * (float)EDIM * 0.01f);
    }

    // ============ PATCH (all gemm blocks, own 64 tokens) ============
    spin_until(&g_pos_done, GDIM);
    spin_until(&g_fill_done, FILL_BLOCKS);
    if (tid < 64) {
        int t = b * 64 + tid;
        int p = __ldcg(&g_pos[t]);
        if (p < C) {
            int e = __ldcg(&g_idx[t]);
            float gv = __ldcg(&g_gate[t]);
            size_t base = ((size_t)t * EDIM + e) * (size_t)C + p;
            out[base]     = gv;
            out[N + base] = 1.0f;
        }
    }
}

// ---------------------------------------------------------------------------
extern "C" void kernel_launch(void* const* d_in, const int* in_sizes, int n_in,
                              void* d_out, int out_size) {
    const float* x  = (const float*)d_in[0];
    const float* Wt = (const float*)d_in[1];
    float* out = (float*)d_out;

    size_t N = ((size_t)out_size - 1) / 2;
    int C = (int)(N / ((size_t)TTOT * EDIM));   // 160

    k_reset<<<1, 1>>>();
    k_fused<<<GRID_TOTAL, 256>>>(x, Wt, out, C, N);
}